// round 1
// baseline (speedup 1.0000x reference)
#include <cuda_runtime.h>
#include <cuda_bf16.h>
#include <math.h>

// Problem constants
#define H     96
#define W     96
#define HW    9216           // H*W
#define C     64
#define NB    12             // 6 backward + 6 forward frame pairs
#define CIN1  130            // warped(64) + x_cur(64) + flow(2)
#define COUT4 432            // 3 * 9 * 16
#define NEG   0.1f

// ---------------------------------------------------------------------------
// Scratch buffers (device globals -- no allocation allowed in kernel_launch)
// ---------------------------------------------------------------------------
__device__ float g_h0[NB * CIN1 * HW];   // concat input  (57.5 MB)
__device__ float g_h1[NB * C * HW];      // conv1 out / conv3 out (28.3 MB)
__device__ float g_h2[NB * C * HW];      // conv2 out            (28.3 MB)
__device__ float g_o4[NB * COUT4 * HW];  // conv4 out            (191 MB)

// ---------------------------------------------------------------------------
// Zero the output (harness poisons d_out; frames bwd[6] and fwd[0] stay 0)
// ---------------------------------------------------------------------------
__global__ void zero_k(float* __restrict__ p, int n) {
    int i = blockIdx.x * blockDim.x + threadIdx.x;
    if (i < n) p[i] = 0.f;
}

// ---------------------------------------------------------------------------
// Stage 1: flow-warp x_src and build concat [warped(64) | x_cur(64) | flow(2)]
// One thread per (n, pixel); bilinear corner setup computed once, reused 64x.
// ---------------------------------------------------------------------------
__global__ void warp_concat_k(const float* __restrict__ x,
                              const float* __restrict__ fb,
                              const float* __restrict__ ff,
                              float* __restrict__ h0) {
    int p = blockIdx.x * blockDim.x + threadIdx.x;
    if (p >= NB * HW) return;
    int n = p / HW, pix = p % HW;
    int yy = pix / W, xx = pix % W;

    int src_t, cur_t;
    const float* flow;
    if (n < 6) { src_t = n + 1; cur_t = n;     flow = fb + (size_t)n * 2 * HW; }
    else       { int m = n - 6; src_t = m; cur_t = m + 1; flow = ff + (size_t)m * 2 * HW; }

    float fx = flow[pix];        // channel 0 = x displacement
    float fy = flow[HW + pix];   // channel 1 = y displacement
    float px = (float)xx + fx;
    float py = (float)yy + fy;

    float y0f = floorf(py), x0f = floorf(px);
    int iy0 = (int)y0f, ix0 = (int)x0f;
    float wy = py - y0f, wx = px - x0f;
    bool vy0 = (iy0 >= 0) && (iy0 < H);
    bool vy1 = (iy0 + 1 >= 0) && (iy0 + 1 < H);
    bool vx0 = (ix0 >= 0) && (ix0 < W);
    bool vx1 = (ix0 + 1 >= 0) && (ix0 + 1 < W);
    int yc0 = min(max(iy0, 0), H - 1),     yc1 = min(max(iy0 + 1, 0), H - 1);
    int xc0 = min(max(ix0, 0), W - 1),     xc1 = min(max(ix0 + 1, 0), W - 1);
    float w00 = (1.f - wy) * (1.f - wx) * ((vy0 && vx0) ? 1.f : 0.f);
    float w01 = (1.f - wy) * wx          * ((vy0 && vx1) ? 1.f : 0.f);
    float w10 = wy * (1.f - wx)          * ((vy1 && vx0) ? 1.f : 0.f);
    float w11 = wy * wx                  * ((vy1 && vx1) ? 1.f : 0.f);
    int i00 = yc0 * W + xc0, i01 = yc0 * W + xc1;
    int i10 = yc1 * W + xc0, i11 = yc1 * W + xc1;

    const float* src = x + (size_t)src_t * C * HW;
    const float* cur = x + (size_t)cur_t * C * HW;
    float* hn = h0 + (size_t)n * CIN1 * HW;

    #pragma unroll 4
    for (int c = 0; c < C; c++) {
        const float* pl = src + (size_t)c * HW;
        float v = w00 * pl[i00] + w01 * pl[i01] + w10 * pl[i10] + w11 * pl[i11];
        hn[(size_t)c * HW + pix]       = v;
        hn[(size_t)(C + c) * HW + pix] = cur[(size_t)c * HW + pix];
    }
    hn[(size_t)128 * HW + pix] = fx;
    hn[(size_t)129 * HW + pix] = fy;
}

// ---------------------------------------------------------------------------
// Generic direct 3x3 conv, pad 1, NCHW fp32.
// Tile: 32x16 pixels. Block (32,4) = 128 threads; each thread owns 4 rows x
// 16 output channels (64 accumulators). Cin processed in chunks of 16 staged
// through shared memory. Per inner step: 64 FFMA vs 20 LDS -> FMA-pipe bound.
// ---------------------------------------------------------------------------
template<bool RELU>
__global__ __launch_bounds__(128) void conv3x3_k(
    const float* __restrict__ in, const float* __restrict__ wt,
    const float* __restrict__ bias, float* __restrict__ out,
    int Cin, int Cout)
{
    __shared__ float s_in[16][18][34];   // [ci][y][x], 39.2 KB
    __shared__ float s_w[16][16][9];     // [co][ci][k],  9.2 KB

    const int tx = threadIdx.x;              // 0..31
    const int ty = threadIdx.y;              // 0..3
    const int tid = ty * 32 + tx;
    const int x0 = blockIdx.x * 32;
    const int y0 = (blockIdx.y % 6) * 16;
    const int n  = blockIdx.y / 6;
    const int co0 = blockIdx.z * 16;
    const float* inN = in + (size_t)n * Cin * HW;

    float acc[4][16];
    #pragma unroll
    for (int r = 0; r < 4; r++)
        #pragma unroll
        for (int o = 0; o < 16; o++) acc[r][o] = 0.f;

    for (int c0 = 0; c0 < Cin; c0 += 16) {
        // Load input tile 16 x 18 x 34 (zero-fill at image border / past Cin)
        for (int i = tid; i < 16 * 18 * 34; i += 128) {
            int ci  = i / (18 * 34);
            int rem = i % (18 * 34);
            int iy = rem / 34, ix = rem % 34;
            int gy = y0 + iy - 1, gx = x0 + ix - 1;
            int c = c0 + ci;
            float v = 0.f;
            if (c < Cin && (unsigned)gy < (unsigned)H && (unsigned)gx < (unsigned)W)
                v = inN[(size_t)c * HW + gy * W + gx];
            s_in[ci][iy][ix] = v;
        }
        // Load weight chunk 16co x 16ci x 9
        for (int i = tid; i < 16 * 16 * 9; i += 128) {
            int co = i / 144, rem = i % 144;
            int ci = rem / 9, k = rem % 9;
            int c = c0 + ci;
            s_w[co][ci][k] = (c < Cin) ? wt[((size_t)(co0 + co) * Cin + c) * 9 + k] : 0.f;
        }
        __syncthreads();

        for (int ci = 0; ci < 16; ci++) {
            #pragma unroll
            for (int k = 0; k < 9; k++) {
                const int ky = k / 3, kx = k % 3;
                float v[4];
                #pragma unroll
                for (int r = 0; r < 4; r++)
                    v[r] = s_in[ci][ty + 4 * r + ky][tx + kx];
                #pragma unroll
                for (int o = 0; o < 16; o++) {
                    float wv = s_w[o][ci][k];
                    #pragma unroll
                    for (int r = 0; r < 4; r++)
                        acc[r][o] += v[r] * wv;
                }
            }
        }
        __syncthreads();
    }

    #pragma unroll
    for (int o = 0; o < 16; o++) {
        float bv = bias[co0 + o];
        #pragma unroll
        for (int r = 0; r < 4; r++) {
            float a = acc[r][o] + bv;
            if (RELU) a = (a >= 0.f) ? a : NEG * a;
            out[((size_t)n * Cout + co0 + o) * HW + (size_t)(y0 + ty + 4 * r) * W + (x0 + tx)] = a;
        }
    }
}

// ---------------------------------------------------------------------------
// Stage 3: fused offset-activation + deformable sampling + 64x576 GEMM.
// Block = 128 threads, 32 pixels of one row.
// Phase 1: 32 pix x 16 dg x 9 kk tasks; each computes tanh/sigmoid-activated
//          offset+mask, bilinear-samples 4 channels of its deform group, and
//          writes samp[idx = c*9+kk][pix] to smem (mask folded into weights).
// Phase 2: smem GEMM out[64co][32pix] = W[64][576] @ samp[576][32];
//          each thread: 4 couts x 4 pixels, weights staged via smem chunks.
// ---------------------------------------------------------------------------
__global__ __launch_bounds__(128) void deform_k(
    const float* __restrict__ x, const float* __restrict__ fb,
    const float* __restrict__ ff, const float* __restrict__ o4,
    const float* __restrict__ dw, const float* __restrict__ db,
    float* __restrict__ out)
{
    extern __shared__ float sm[];
    float* samp = sm;                 // [576][36]  (82.9 KB, float4-friendly)
    float* s_w  = sm + 576 * 36;      // [64][73]   (18.7 KB, pad kills conflicts)

    const int tid = threadIdx.x;
    const int n   = blockIdx.z;
    const int y   = blockIdx.y;
    const int xb  = blockIdx.x * 32;

    int src_t;
    const float* flow;
    if (n < 6) { src_t = n + 1; flow = fb + (size_t)n * 2 * HW; }
    else       { src_t = n - 6; flow = ff + (size_t)(n - 6) * 2 * HW; }
    const float* src = x + (size_t)src_t * C * HW;
    const float* o4n = o4 + (size_t)n * COUT4 * HW;

    // -------- Phase 1: offsets + bilinear sampling --------
    for (int task = tid; task < 32 * 144; task += 128) {
        int pix  = task & 31;
        int dgkk = task >> 5;         // 0..143
        int dg = dgkk / 9, kk = dgkk % 9;
        int xx = xb + pix;
        int pp = y * W + xx;

        float fx = flow[pp];
        float fy = flow[HW + pp];
        float t0 = o4n[(size_t)(dg * 18 + kk * 2)     * HW + pp];  // raw dy
        float t1 = o4n[(size_t)(dg * 18 + kk * 2 + 1) * HW + pp];  // raw dx
        float tm = o4n[(size_t)(288 + dg * 9 + kk)    * HW + pp];  // raw mask
        float m  = 1.f / (1.f + expf(-tm));
        float py = 10.f * tanhf(t0) + fy + (float)(y  - 1 + kk / 3);
        float px = 10.f * tanhf(t1) + fx + (float)(xx - 1 + kk % 3);

        float y0f = floorf(py), x0f = floorf(px);
        int iy0 = (int)y0f, ix0 = (int)x0f;
        float wy = py - y0f, wx = px - x0f;
        bool vy0 = (iy0 >= 0) && (iy0 < H);
        bool vy1 = (iy0 + 1 >= 0) && (iy0 + 1 < H);
        bool vx0 = (ix0 >= 0) && (ix0 < W);
        bool vx1 = (ix0 + 1 >= 0) && (ix0 + 1 < W);
        int yc0 = min(max(iy0, 0), H - 1),     yc1 = min(max(iy0 + 1, 0), H - 1);
        int xc0 = min(max(ix0, 0), W - 1),     xc1 = min(max(ix0 + 1, 0), W - 1);
        float w00 = (1.f - wy) * (1.f - wx) * ((vy0 && vx0) ? m : 0.f);
        float w01 = (1.f - wy) * wx          * ((vy0 && vx1) ? m : 0.f);
        float w10 = wy * (1.f - wx)          * ((vy1 && vx0) ? m : 0.f);
        float w11 = wy * wx                  * ((vy1 && vx1) ? m : 0.f);
        int i00 = yc0 * W + xc0, i01 = yc0 * W + xc1;
        int i10 = yc1 * W + xc0, i11 = yc1 * W + xc1;

        #pragma unroll
        for (int cg = 0; cg < 4; cg++) {
            const float* pl = src + (size_t)(dg * 4 + cg) * HW;
            float v = w00 * pl[i00] + w01 * pl[i01] + w10 * pl[i10] + w11 * pl[i11];
            samp[(size_t)((dg * 4 + cg) * 9 + kk) * 36 + pix] = v;
        }
    }
    __syncthreads();

    // -------- Phase 2: out[co][pix] = sum_idx W[co][idx] * samp[idx][pix] ----
    const int pg = tid & 7;     // pixel group: pixels pg*4 .. pg*4+3
    const int og = tid >> 3;    // cout group:  couts  og*4 .. og*4+3
    float acc[4][4];
    #pragma unroll
    for (int o = 0; o < 4; o++)
        #pragma unroll
        for (int p = 0; p < 4; p++) acc[o][p] = 0.f;

    for (int ch = 0; ch < 576; ch += 72) {
        for (int i = tid; i < 64 * 72; i += 128) {
            int co = i / 72, ii = i % 72;
            s_w[co * 73 + ii] = dw[(size_t)co * 576 + ch + ii];
        }
        __syncthreads();
        for (int ii = 0; ii < 72; ii++) {
            float4 sv = *(const float4*)&samp[(size_t)(ch + ii) * 36 + pg * 4];
            #pragma unroll
            for (int o = 0; o < 4; o++) {
                float wv = s_w[(og * 4 + o) * 73 + ii];
                acc[o][0] += wv * sv.x;
                acc[o][1] += wv * sv.y;
                acc[o][2] += wv * sv.z;
                acc[o][3] += wv * sv.w;
            }
        }
        __syncthreads();
    }

    // Output placement: bwd n -> x_backward frame n; fwd m -> x_forward frame m+1
    float* outn = (n < 6) ? out + (size_t)n * C * HW
                          : out + (size_t)(7 + (n - 6) + 1) * C * HW;
    #pragma unroll
    for (int o = 0; o < 4; o++) {
        int co = og * 4 + o;
        float bv = db[co];
        #pragma unroll
        for (int p = 0; p < 4; p++)
            outn[(size_t)co * HW + (size_t)y * W + (xb + pg * 4 + p)] = acc[o][p] + bv;
    }
}

// ---------------------------------------------------------------------------
// Launch
// ---------------------------------------------------------------------------
extern "C" void kernel_launch(void* const* d_in, const int* in_sizes, int n_in,
                              void* d_out, int out_size)
{
    const float* x  = (const float*)d_in[0];
    const float* fb = (const float*)d_in[1];
    const float* ff = (const float*)d_in[2];
    const float* w1 = (const float*)d_in[3];  const float* b1 = (const float*)d_in[4];
    const float* w2 = (const float*)d_in[5];  const float* b2 = (const float*)d_in[6];
    const float* w3 = (const float*)d_in[7];  const float* b3 = (const float*)d_in[8];
    const float* w4 = (const float*)d_in[9];  const float* b4 = (const float*)d_in[10];
    const float* dw = (const float*)d_in[11]; const float* db = (const float*)d_in[12];
    float* out = (float*)d_out;

    float *h0, *h1, *h2, *o4;
    cudaGetSymbolAddress((void**)&h0, g_h0);
    cudaGetSymbolAddress((void**)&h1, g_h1);
    cudaGetSymbolAddress((void**)&h2, g_h2);
    cudaGetSymbolAddress((void**)&o4, g_o4);

    zero_k<<<(out_size + 1023) / 1024, 1024>>>(out, out_size);
    warp_concat_k<<<(NB * HW + 255) / 256, 256>>>(x, fb, ff, h0);

    dim3 cb(32, 4);
    conv3x3_k<true ><<<dim3(3, 72, 4),  cb>>>(h0, w1, b1, h1, CIN1, C);
    conv3x3_k<true ><<<dim3(3, 72, 4),  cb>>>(h1, w2, b2, h2, C,    C);
    conv3x3_k<true ><<<dim3(3, 72, 4),  cb>>>(h2, w3, b3, h1, C,    C);
    conv3x3_k<false><<<dim3(3, 72, 27), cb>>>(h1, w4, b4, o4, C, COUT4);

    const int dsm = (576 * 36 + 64 * 73) * (int)sizeof(float);  // 101,632 B
    cudaFuncSetAttribute(deform_k, cudaFuncAttributeMaxDynamicSharedMemorySize, dsm);
    deform_k<<<dim3(3, 96, NB), 128, dsm>>>(x, fb, ff, o4, dw, db, out);
}

// round 2
// speedup vs baseline: 1.0577x; 1.0577x over previous
#include <cuda_runtime.h>
#include <cuda_bf16.h>
#include <math.h>

// Problem constants
#define H     96
#define W     96
#define HW    9216           // H*W
#define C     64
#define NB    12             // 6 backward + 6 forward frame pairs
#define CIN1  130            // warped(64) + x_cur(64) + flow(2)
#define COUT4 432            // 3 * 9 * 16
#define NEG   0.1f

// ---------------------------------------------------------------------------
// Packed fp32x2 helpers (sm_100a FFMA2 path — 2 fp32 FMAs per issue slot)
// ---------------------------------------------------------------------------
__device__ __forceinline__ void ffma2(unsigned long long& d,
                                      unsigned long long a,
                                      unsigned long long b) {
    asm("fma.rn.f32x2 %0, %1, %2, %0;" : "+l"(d) : "l"(a), "l"(b));
}
__device__ __forceinline__ unsigned long long pack2(float lo, float hi) {
    unsigned long long r;
    asm("mov.b64 %0, {%1, %2};" : "=l"(r) : "f"(lo), "f"(hi));
    return r;
}
__device__ __forceinline__ float2 unpack2(unsigned long long v) {
    float2 r;
    asm("mov.b64 {%0, %1}, %2;" : "=f"(r.x), "=f"(r.y) : "l"(v));
    return r;
}

// ---------------------------------------------------------------------------
// Scratch buffers (device globals -- no allocation allowed in kernel_launch)
// ---------------------------------------------------------------------------
__device__ float g_h0[NB * CIN1 * HW];   // concat input
__device__ float g_h1[NB * C * HW];      // conv1 out / conv3 out
__device__ float g_h2[NB * C * HW];      // conv2 out
__device__ float g_o4[NB * COUT4 * HW];  // conv4 out

// ---------------------------------------------------------------------------
// Zero only the two frames deform never writes (bwd[6], fwd[0] -> contiguous
// region frames 6..7 of the 14-frame output).
// ---------------------------------------------------------------------------
__global__ void zero_k(float4* __restrict__ p, int n4) {
    int i = blockIdx.x * blockDim.x + threadIdx.x;
    if (i < n4) p[i] = make_float4(0.f, 0.f, 0.f, 0.f);
}

// ---------------------------------------------------------------------------
// Stage 1: flow-warp x_src and build concat [warped(64) | x_cur(64) | flow(2)]
// ---------------------------------------------------------------------------
__global__ void warp_concat_k(const float* __restrict__ x,
                              const float* __restrict__ fb,
                              const float* __restrict__ ff,
                              float* __restrict__ h0) {
    int p = blockIdx.x * blockDim.x + threadIdx.x;
    if (p >= NB * HW) return;
    int n = p / HW, pix = p % HW;
    int yy = pix / W, xx = pix % W;

    int src_t, cur_t;
    const float* flow;
    if (n < 6) { src_t = n + 1; cur_t = n;     flow = fb + (size_t)n * 2 * HW; }
    else       { int m = n - 6; src_t = m; cur_t = m + 1; flow = ff + (size_t)m * 2 * HW; }

    float fx = flow[pix];
    float fy = flow[HW + pix];
    float px = (float)xx + fx;
    float py = (float)yy + fy;

    float y0f = floorf(py), x0f = floorf(px);
    int iy0 = (int)y0f, ix0 = (int)x0f;
    float wy = py - y0f, wx = px - x0f;
    bool vy0 = (iy0 >= 0) && (iy0 < H);
    bool vy1 = (iy0 + 1 >= 0) && (iy0 + 1 < H);
    bool vx0 = (ix0 >= 0) && (ix0 < W);
    bool vx1 = (ix0 + 1 >= 0) && (ix0 + 1 < W);
    int yc0 = min(max(iy0, 0), H - 1),     yc1 = min(max(iy0 + 1, 0), H - 1);
    int xc0 = min(max(ix0, 0), W - 1),     xc1 = min(max(ix0 + 1, 0), W - 1);
    float w00 = (1.f - wy) * (1.f - wx) * ((vy0 && vx0) ? 1.f : 0.f);
    float w01 = (1.f - wy) * wx          * ((vy0 && vx1) ? 1.f : 0.f);
    float w10 = wy * (1.f - wx)          * ((vy1 && vx0) ? 1.f : 0.f);
    float w11 = wy * wx                  * ((vy1 && vx1) ? 1.f : 0.f);
    int i00 = yc0 * W + xc0, i01 = yc0 * W + xc1;
    int i10 = yc1 * W + xc0, i11 = yc1 * W + xc1;

    const float* src = x + (size_t)src_t * C * HW;
    const float* cur = x + (size_t)cur_t * C * HW;
    float* hn = h0 + (size_t)n * CIN1 * HW;

    #pragma unroll 4
    for (int c = 0; c < C; c++) {
        const float* pl = src + (size_t)c * HW;
        float v = w00 * pl[i00] + w01 * pl[i01] + w10 * pl[i10] + w11 * pl[i11];
        hn[(size_t)c * HW + pix]       = v;
        hn[(size_t)(C + c) * HW + pix] = cur[(size_t)c * HW + pix];
    }
    hn[(size_t)128 * HW + pix] = fx;
    hn[(size_t)129 * HW + pix] = fy;
}

// ---------------------------------------------------------------------------
// Direct 3x3 conv, pad 1, NCHW fp32, FFMA2 inner loop.
// Tile 32x16 px, block (32,4); each thread: 4 rows x 8 cout-pairs (16 couts).
// Weights staged [ci][k][co] so a cout-pair is one aligned LDS64; the pixel
// value is duplicated into both f32x2 lanes (one mov.b64).
// Per (ci,k): 4 LDS + 4 pack + 8 LDS64 + 32 FFMA2 (=64 MACs).
// ---------------------------------------------------------------------------
template<bool RELU>
__global__ __launch_bounds__(128) void conv3x3_k(
    const float* __restrict__ in, const float* __restrict__ wt,
    const float* __restrict__ bias, float* __restrict__ out,
    int Cin, int Cout)
{
    __shared__ float s_in[16][18][34];   // [ci][y][x]   39.2 KB
    __shared__ float s_w[16][9][16];     // [ci][k][co]   9.2 KB

    const int tx = threadIdx.x;              // 0..31
    const int ty = threadIdx.y;              // 0..3
    const int tid = ty * 32 + tx;
    const int x0 = blockIdx.x * 32;
    const int y0 = (blockIdx.y % 6) * 16;
    const int n  = blockIdx.y / 6;
    const int co0 = blockIdx.z * 16;
    const float* inN = in + (size_t)n * Cin * HW;

    unsigned long long acc[4][8];
    #pragma unroll
    for (int r = 0; r < 4; r++)
        #pragma unroll
        for (int o = 0; o < 8; o++) acc[r][o] = 0ull;

    for (int c0 = 0; c0 < Cin; c0 += 16) {
        // Input tile 16 x 18 x 34 (zero-fill at image border / past Cin)
        for (int i = tid; i < 16 * 18 * 34; i += 128) {
            int ci  = i / (18 * 34);
            int rem = i % (18 * 34);
            int iy = rem / 34, ix = rem % 34;
            int gy = y0 + iy - 1, gx = x0 + ix - 1;
            int c = c0 + ci;
            float v = 0.f;
            if (c < Cin && (unsigned)gy < (unsigned)H && (unsigned)gx < (unsigned)W)
                v = inN[(size_t)c * HW + gy * W + gx];
            s_in[ci][iy][ix] = v;
        }
        // Weight chunk, transposed to [ci][k][co]
        for (int i = tid; i < 16 * 16 * 9; i += 128) {
            int co = i / 144, rem = i % 144;
            int ci = rem / 9, k = rem % 9;
            int c = c0 + ci;
            s_w[ci][k][co] = (c < Cin) ? wt[((size_t)(co0 + co) * Cin + c) * 9 + k] : 0.f;
        }
        __syncthreads();

        for (int ci = 0; ci < 16; ci++) {
            #pragma unroll
            for (int k = 0; k < 9; k++) {
                const int ky = k / 3, kx = k % 3;
                unsigned long long vv[4];
                #pragma unroll
                for (int r = 0; r < 4; r++) {
                    float v = s_in[ci][ty + 4 * r + ky][tx + kx];
                    vv[r] = pack2(v, v);
                }
                #pragma unroll
                for (int o = 0; o < 8; o++) {
                    unsigned long long wp =
                        *(const unsigned long long*)&s_w[ci][k][2 * o];
                    #pragma unroll
                    for (int r = 0; r < 4; r++)
                        ffma2(acc[r][o], vv[r], wp);
                }
            }
        }
        __syncthreads();
    }

    #pragma unroll
    for (int o = 0; o < 8; o++) {
        float b0 = bias[co0 + 2 * o];
        float b1 = bias[co0 + 2 * o + 1];
        #pragma unroll
        for (int r = 0; r < 4; r++) {
            float2 a = unpack2(acc[r][o]);
            a.x += b0; a.y += b1;
            if (RELU) {
                a.x = (a.x >= 0.f) ? a.x : NEG * a.x;
                a.y = (a.y >= 0.f) ? a.y : NEG * a.y;
            }
            size_t base = (size_t)(y0 + ty + 4 * r) * W + (x0 + tx);
            out[((size_t)n * Cout + co0 + 2 * o)     * HW + base] = a.x;
            out[((size_t)n * Cout + co0 + 2 * o + 1) * HW + base] = a.y;
        }
    }
}

// ---------------------------------------------------------------------------
// Stage 3: fused offset-activation + deformable sampling + 64x576 GEMM.
// Phase 2 now FFMA2: weights pre-duplicated {w,w} in smem (LDS64 broadcast);
// the samp float4 is loaded as ulonglong2 = two ready f32x2 pixel pairs.
// Per inner step: 1 LDS128 + 4 LDS64 + 8 FFMA2 (=32 MACs).
// ---------------------------------------------------------------------------
__global__ __launch_bounds__(128) void deform_k(
    const float* __restrict__ x, const float* __restrict__ fb,
    const float* __restrict__ ff, const float* __restrict__ o4,
    const float* __restrict__ dw, const float* __restrict__ db,
    float* __restrict__ out)
{
    extern __shared__ float sm[];
    float*  samp = sm;                       // [576][36]  82.9 KB
    float2* s_w2 = (float2*)(sm + 576 * 36); // [64][37] dup pairs, 18.9 KB

    const int tid = threadIdx.x;
    const int n   = blockIdx.z;
    const int y   = blockIdx.y;
    const int xb  = blockIdx.x * 32;

    int src_t;
    const float* flow;
    if (n < 6) { src_t = n + 1; flow = fb + (size_t)n * 2 * HW; }
    else       { src_t = n - 6; flow = ff + (size_t)(n - 6) * 2 * HW; }
    const float* src = x + (size_t)src_t * C * HW;
    const float* o4n = o4 + (size_t)n * COUT4 * HW;

    // -------- Phase 1: offsets + bilinear sampling --------
    for (int task = tid; task < 32 * 144; task += 128) {
        int pix  = task & 31;
        int dgkk = task >> 5;
        int dg = dgkk / 9, kk = dgkk % 9;
        int xx = xb + pix;
        int pp = y * W + xx;

        float fx = flow[pp];
        float fy = flow[HW + pp];
        float t0 = o4n[(size_t)(dg * 18 + kk * 2)     * HW + pp];
        float t1 = o4n[(size_t)(dg * 18 + kk * 2 + 1) * HW + pp];
        float tm = o4n[(size_t)(288 + dg * 9 + kk)    * HW + pp];
        float m  = 1.f / (1.f + expf(-tm));
        float py = 10.f * tanhf(t0) + fy + (float)(y  - 1 + kk / 3);
        float px = 10.f * tanhf(t1) + fx + (float)(xx - 1 + kk % 3);

        float y0f = floorf(py), x0f = floorf(px);
        int iy0 = (int)y0f, ix0 = (int)x0f;
        float wy = py - y0f, wx = px - x0f;
        bool vy0 = (iy0 >= 0) && (iy0 < H);
        bool vy1 = (iy0 + 1 >= 0) && (iy0 + 1 < H);
        bool vx0 = (ix0 >= 0) && (ix0 < W);
        bool vx1 = (ix0 + 1 >= 0) && (ix0 + 1 < W);
        int yc0 = min(max(iy0, 0), H - 1),     yc1 = min(max(iy0 + 1, 0), H - 1);
        int xc0 = min(max(ix0, 0), W - 1),     xc1 = min(max(ix0 + 1, 0), W - 1);
        float w00 = (1.f - wy) * (1.f - wx) * ((vy0 && vx0) ? m : 0.f);
        float w01 = (1.f - wy) * wx          * ((vy0 && vx1) ? m : 0.f);
        float w10 = wy * (1.f - wx)          * ((vy1 && vx0) ? m : 0.f);
        float w11 = wy * wx                  * ((vy1 && vx1) ? m : 0.f);
        int i00 = yc0 * W + xc0, i01 = yc0 * W + xc1;
        int i10 = yc1 * W + xc0, i11 = yc1 * W + xc1;

        #pragma unroll
        for (int cg = 0; cg < 4; cg++) {
            const float* pl = src + (size_t)(dg * 4 + cg) * HW;
            float v = w00 * pl[i00] + w01 * pl[i01] + w10 * pl[i10] + w11 * pl[i11];
            samp[(size_t)((dg * 4 + cg) * 9 + kk) * 36 + pix] = v;
        }
    }
    __syncthreads();

    // -------- Phase 2: out[64co][32px] = W[64][576] @ samp[576][32] ----------
    const int pg = tid & 7;     // pixels pg*4 .. pg*4+3 (two f32x2 pairs)
    const int og = tid >> 3;    // couts  og*4 .. og*4+3
    unsigned long long acc[4][2];
    #pragma unroll
    for (int o = 0; o < 4; o++) { acc[o][0] = 0ull; acc[o][1] = 0ull; }

    for (int ch = 0; ch < 576; ch += 36) {
        for (int i = tid; i < 64 * 36; i += 128) {
            int co = i / 36, ii = i % 36;
            float w = dw[(size_t)co * 576 + ch + ii];
            s_w2[co * 37 + ii] = make_float2(w, w);
        }
        __syncthreads();
        #pragma unroll 4
        for (int ii = 0; ii < 36; ii++) {
            ulonglong2 sv = *(const ulonglong2*)&samp[(size_t)(ch + ii) * 36 + pg * 4];
            #pragma unroll
            for (int o = 0; o < 4; o++) {
                unsigned long long wp =
                    *(const unsigned long long*)&s_w2[(og * 4 + o) * 37 + ii];
                ffma2(acc[o][0], wp, sv.x);
                ffma2(acc[o][1], wp, sv.y);
            }
        }
        __syncthreads();
    }

    // Output placement: bwd n -> x_backward frame n; fwd m -> x_forward frame m+1
    float* outn = (n < 6) ? out + (size_t)n * C * HW
                          : out + (size_t)(7 + (n - 6) + 1) * C * HW;
    #pragma unroll
    for (int o = 0; o < 4; o++) {
        int co = og * 4 + o;
        float bv = db[co];
        float2 a0 = unpack2(acc[o][0]);
        float2 a1 = unpack2(acc[o][1]);
        size_t base = (size_t)co * HW + (size_t)y * W + (xb + pg * 4);
        outn[base + 0] = a0.x + bv;
        outn[base + 1] = a0.y + bv;
        outn[base + 2] = a1.x + bv;
        outn[base + 3] = a1.y + bv;
    }
}

// ---------------------------------------------------------------------------
// Launch
// ---------------------------------------------------------------------------
extern "C" void kernel_launch(void* const* d_in, const int* in_sizes, int n_in,
                              void* d_out, int out_size)
{
    const float* x  = (const float*)d_in[0];
    const float* fb = (const float*)d_in[1];
    const float* ff = (const float*)d_in[2];
    const float* w1 = (const float*)d_in[3];  const float* b1 = (const float*)d_in[4];
    const float* w2 = (const float*)d_in[5];  const float* b2 = (const float*)d_in[6];
    const float* w3 = (const float*)d_in[7];  const float* b3 = (const float*)d_in[8];
    const float* w4 = (const float*)d_in[9];  const float* b4 = (const float*)d_in[10];
    const float* dw = (const float*)d_in[11]; const float* db = (const float*)d_in[12];
    float* out = (float*)d_out;

    float *h0, *h1, *h2, *o4;
    cudaGetSymbolAddress((void**)&h0, g_h0);
    cudaGetSymbolAddress((void**)&h1, g_h1);
    cudaGetSymbolAddress((void**)&h2, g_h2);
    cudaGetSymbolAddress((void**)&o4, g_o4);

    // Zero only frames 6..7 (bwd[6] and fwd[0]); deform writes everything else.
    {
        int n4 = 2 * C * HW / 4;
        zero_k<<<(n4 + 255) / 256, 256>>>((float4*)(out + (size_t)6 * C * HW), n4);
    }
    warp_concat_k<<<(NB * HW + 255) / 256, 256>>>(x, fb, ff, h0);

    dim3 cb(32, 4);
    conv3x3_k<true ><<<dim3(3, 72, 4),  cb>>>(h0, w1, b1, h1, CIN1, C);
    conv3x3_k<true ><<<dim3(3, 72, 4),  cb>>>(h1, w2, b2, h2, C,    C);
    conv3x3_k<true ><<<dim3(3, 72, 4),  cb>>>(h2, w3, b3, h1, C,    C);
    conv3x3_k<false><<<dim3(3, 72, 27), cb>>>(h1, w4, b4, o4, C, COUT4);

    const int dsm = (576 * 36) * (int)sizeof(float) + 64 * 37 * (int)sizeof(float2);
    cudaFuncSetAttribute(deform_k, cudaFuncAttributeMaxDynamicSharedMemorySize, dsm);
    deform_k<<<dim3(3, 96, NB), 128, dsm>>>(x, fb, ff, o4, dw, db, out);
}

// round 4
// speedup vs baseline: 1.2268x; 1.1599x over previous
#include <cuda_runtime.h>
#include <cuda_bf16.h>
#include <math.h>

// Problem constants
#define H     96
#define W     96
#define HW    9216           // H*W
#define C     64
#define NB    12             // 6 backward + 6 forward frame pairs
#define CIN1  130            // warped(64) + x_cur(64) + flow(2)
#define COUT4 432            // 3 * 9 * 16
#define NEG   0.1f

// ---------------------------------------------------------------------------
// Packed fp32x2 helpers (sm_100a FFMA2 path — 2 fp32 FMAs per issue slot)
// ---------------------------------------------------------------------------
__device__ __forceinline__ void ffma2(unsigned long long& d,
                                      unsigned long long a,
                                      unsigned long long b) {
    asm("fma.rn.f32x2 %0, %1, %2, %0;" : "+l"(d) : "l"(a), "l"(b));
}
__device__ __forceinline__ unsigned long long pack2(float lo, float hi) {
    unsigned long long r;
    asm("mov.b64 %0, {%1, %2};" : "=l"(r) : "f"(lo), "f"(hi));
    return r;
}
__device__ __forceinline__ float2 unpack2(unsigned long long v) {
    float2 r;
    asm("mov.b64 {%0, %1}, %2;" : "=f"(r.x), "=f"(r.y) : "l"(v));
    return r;
}

// Fast tanh / sigmoid built on MUFU EX2/RCP (rel err ~1e-6; offsets scale x10
// so position error ~1e-5 px — negligible vs the 1e-3 rel-err budget).
__device__ __forceinline__ float fast_tanh(float x) {
    float xc = fminf(fmaxf(x, -15.f), 15.f);
    float e = __expf(2.f * xc);
    return __fdividef(e - 1.f, e + 1.f);
}
__device__ __forceinline__ float fast_sigmoid(float x) {
    float xc = fminf(fmaxf(x, -30.f), 30.f);
    return __fdividef(1.f, 1.f + __expf(-xc));
}

// ---------------------------------------------------------------------------
// Scratch buffers (device globals -- no allocation allowed in kernel_launch)
// ---------------------------------------------------------------------------
__device__ float g_h0[NB * CIN1 * HW];    // concat input
__device__ float g_h1[NB * C * HW];       // conv1 out / conv3 out
__device__ float g_h2[NB * C * HW];       // conv2 out
__device__ float g_o4[NB * COUT4 * HW];   // conv4 out
__device__ float g_samp[NB * 576 * HW];   // deform samples (255 MB)

// ---------------------------------------------------------------------------
// Zero only the two frames deform never writes (bwd[6], fwd[0])
// ---------------------------------------------------------------------------
__global__ void zero_k(float4* __restrict__ p, int n4) {
    int i = blockIdx.x * blockDim.x + threadIdx.x;
    if (i < n4) p[i] = make_float4(0.f, 0.f, 0.f, 0.f);
}

// ---------------------------------------------------------------------------
// Stage 1: flow-warp x_src and build concat [warped(64) | x_cur(64) | flow(2)]
// ---------------------------------------------------------------------------
__global__ void warp_concat_k(const float* __restrict__ x,
                              const float* __restrict__ fb,
                              const float* __restrict__ ff,
                              float* __restrict__ h0) {
    int p = blockIdx.x * blockDim.x + threadIdx.x;
    if (p >= NB * HW) return;
    int n = p / HW, pix = p % HW;
    int yy = pix / W, xx = pix % W;

    int src_t, cur_t;
    const float* flow;
    if (n < 6) { src_t = n + 1; cur_t = n;     flow = fb + (size_t)n * 2 * HW; }
    else       { int m = n - 6; src_t = m; cur_t = m + 1; flow = ff + (size_t)m * 2 * HW; }

    float fx = flow[pix];
    float fy = flow[HW + pix];
    float px = (float)xx + fx;
    float py = (float)yy + fy;

    float y0f = floorf(py), x0f = floorf(px);
    int iy0 = (int)y0f, ix0 = (int)x0f;
    float wy = py - y0f, wx = px - x0f;
    bool vy0 = (iy0 >= 0) && (iy0 < H);
    bool vy1 = (iy0 + 1 >= 0) && (iy0 + 1 < H);
    bool vx0 = (ix0 >= 0) && (ix0 < W);
    bool vx1 = (ix0 + 1 >= 0) && (ix0 + 1 < W);
    int yc0 = min(max(iy0, 0), H - 1),     yc1 = min(max(iy0 + 1, 0), H - 1);
    int xc0 = min(max(ix0, 0), W - 1),     xc1 = min(max(ix0 + 1, 0), W - 1);
    float w00 = (1.f - wy) * (1.f - wx) * ((vy0 && vx0) ? 1.f : 0.f);
    float w01 = (1.f - wy) * wx          * ((vy0 && vx1) ? 1.f : 0.f);
    float w10 = wy * (1.f - wx)          * ((vy1 && vx0) ? 1.f : 0.f);
    float w11 = wy * wx                  * ((vy1 && vx1) ? 1.f : 0.f);
    int i00 = yc0 * W + xc0, i01 = yc0 * W + xc1;
    int i10 = yc1 * W + xc0, i11 = yc1 * W + xc1;

    const float* src = x + (size_t)src_t * C * HW;
    const float* cur = x + (size_t)cur_t * C * HW;
    float* hn = h0 + (size_t)n * CIN1 * HW;

    #pragma unroll 4
    for (int c = 0; c < C; c++) {
        const float* pl = src + (size_t)c * HW;
        float v = w00 * pl[i00] + w01 * pl[i01] + w10 * pl[i10] + w11 * pl[i11];
        hn[(size_t)c * HW + pix]       = v;
        hn[(size_t)(C + c) * HW + pix] = cur[(size_t)c * HW + pix];
    }
    hn[(size_t)128 * HW + pix] = fx;
    hn[(size_t)129 * HW + pix] = fy;
}

// ---------------------------------------------------------------------------
// Direct 3x3 conv, pad 1, NCHW fp32, FFMA2 inner loop (at FFMA2 roofline).
// ---------------------------------------------------------------------------
template<bool RELU>
__global__ __launch_bounds__(128) void conv3x3_k(
    const float* __restrict__ in, const float* __restrict__ wt,
    const float* __restrict__ bias, float* __restrict__ out,
    int Cin, int Cout)
{
    __shared__ float s_in[16][18][34];   // [ci][y][x]   39.2 KB
    __shared__ float s_w[16][9][16];     // [ci][k][co]   9.2 KB

    const int tx = threadIdx.x;
    const int ty = threadIdx.y;
    const int tid = ty * 32 + tx;
    const int x0 = blockIdx.x * 32;
    const int y0 = (blockIdx.y % 6) * 16;
    const int n  = blockIdx.y / 6;
    const int co0 = blockIdx.z * 16;
    const float* inN = in + (size_t)n * Cin * HW;

    unsigned long long acc[4][8];
    #pragma unroll
    for (int r = 0; r < 4; r++)
        #pragma unroll
        for (int o = 0; o < 8; o++) acc[r][o] = 0ull;

    for (int c0 = 0; c0 < Cin; c0 += 16) {
        for (int i = tid; i < 16 * 18 * 34; i += 128) {
            int ci  = i / (18 * 34);
            int rem = i % (18 * 34);
            int iy = rem / 34, ix = rem % 34;
            int gy = y0 + iy - 1, gx = x0 + ix - 1;
            int c = c0 + ci;
            float v = 0.f;
            if (c < Cin && (unsigned)gy < (unsigned)H && (unsigned)gx < (unsigned)W)
                v = inN[(size_t)c * HW + gy * W + gx];
            s_in[ci][iy][ix] = v;
        }
        for (int i = tid; i < 16 * 16 * 9; i += 128) {
            int co = i / 144, rem = i % 144;
            int ci = rem / 9, k = rem % 9;
            int c = c0 + ci;
            s_w[ci][k][co] = (c < Cin) ? wt[((size_t)(co0 + co) * Cin + c) * 9 + k] : 0.f;
        }
        __syncthreads();

        for (int ci = 0; ci < 16; ci++) {
            #pragma unroll
            for (int k = 0; k < 9; k++) {
                const int ky = k / 3, kx = k % 3;
                unsigned long long vv[4];
                #pragma unroll
                for (int r = 0; r < 4; r++) {
                    float v = s_in[ci][ty + 4 * r + ky][tx + kx];
                    vv[r] = pack2(v, v);
                }
                #pragma unroll
                for (int o = 0; o < 8; o++) {
                    unsigned long long wp =
                        *(const unsigned long long*)&s_w[ci][k][2 * o];
                    #pragma unroll
                    for (int r = 0; r < 4; r++)
                        ffma2(acc[r][o], vv[r], wp);
                }
            }
        }
        __syncthreads();
    }

    #pragma unroll
    for (int o = 0; o < 8; o++) {
        float b0 = bias[co0 + 2 * o];
        float b1 = bias[co0 + 2 * o + 1];
        #pragma unroll
        for (int r = 0; r < 4; r++) {
            float2 a = unpack2(acc[r][o]);
            a.x += b0; a.y += b1;
            if (RELU) {
                a.x = (a.x >= 0.f) ? a.x : NEG * a.x;
                a.y = (a.y >= 0.f) ? a.y : NEG * a.y;
            }
            size_t base = (size_t)(y0 + ty + 4 * r) * W + (x0 + tx);
            out[((size_t)n * Cout + co0 + 2 * o)     * HW + base] = a.x;
            out[((size_t)n * Cout + co0 + 2 * o + 1) * HW + base] = a.y;
        }
    }
}

// ---------------------------------------------------------------------------
// Deform stage A: offsets + bilinear sampling -> g_samp[n][576][HW].
// No smem, full occupancy. One thread per (n, dg, pixel); 9 taps each.
// ---------------------------------------------------------------------------
__global__ __launch_bounds__(128) void sample_k(
    const float* __restrict__ x, const float* __restrict__ fb,
    const float* __restrict__ ff, const float* __restrict__ o4,
    float* __restrict__ samp)
{
    const int pix = blockIdx.x * 128 + threadIdx.x;
    const int dg  = blockIdx.y;
    const int n   = blockIdx.z;
    const int y   = pix / W;
    const int xx  = pix % W;

    int src_t;
    const float* flow;
    if (n < 6) { src_t = n + 1; flow = fb + (size_t)n * 2 * HW; }
    else       { src_t = n - 6; flow = ff + (size_t)(n - 6) * 2 * HW; }
    const float* src   = x + (size_t)src_t * C * HW + (size_t)dg * 4 * HW;
    const float* o4n   = o4 + (size_t)n * COUT4 * HW + pix;
    float*       sampn = samp + (size_t)n * 576 * HW + (size_t)dg * 36 * HW + pix;

    const float fx = flow[pix];
    const float fy = flow[HW + pix];

    #pragma unroll
    for (int kk = 0; kk < 9; kk++) {
        float t0 = o4n[(size_t)(dg * 18 + kk * 2)     * HW];
        float t1 = o4n[(size_t)(dg * 18 + kk * 2 + 1) * HW];
        float tm = o4n[(size_t)(288 + dg * 9 + kk)    * HW];
        float m  = fast_sigmoid(tm);
        float py = 10.f * fast_tanh(t0) + fy + (float)(y  - 1 + kk / 3);
        float px = 10.f * fast_tanh(t1) + fx + (float)(xx - 1 + kk % 3);

        float y0f = floorf(py), x0f = floorf(px);
        int iy0 = (int)y0f, ix0 = (int)x0f;
        float wy = py - y0f, wx = px - x0f;
        bool vy0 = (iy0 >= 0) && (iy0 < H);
        bool vy1 = (iy0 + 1 >= 0) && (iy0 + 1 < H);
        bool vx0 = (ix0 >= 0) && (ix0 < W);
        bool vx1 = (ix0 + 1 >= 0) && (ix0 + 1 < W);
        int yc0 = min(max(iy0, 0), H - 1),     yc1 = min(max(iy0 + 1, 0), H - 1);
        int xc0 = min(max(ix0, 0), W - 1),     xc1 = min(max(ix0 + 1, 0), W - 1);
        float w00 = (1.f - wy) * (1.f - wx) * ((vy0 && vx0) ? m : 0.f);
        float w01 = (1.f - wy) * wx          * ((vy0 && vx1) ? m : 0.f);
        float w10 = wy * (1.f - wx)          * ((vy1 && vx0) ? m : 0.f);
        float w11 = wy * wx                  * ((vy1 && vx1) ? m : 0.f);
        int i00 = yc0 * W + xc0, i01 = yc0 * W + xc1;
        int i10 = yc1 * W + xc0, i11 = yc1 * W + xc1;

        #pragma unroll
        for (int cg = 0; cg < 4; cg++) {
            const float* pl = src + (size_t)cg * HW;
            float v = w00 * pl[i00] + w01 * pl[i01] + w10 * pl[i10] + w11 * pl[i11];
            sampn[(size_t)(cg * 9 + kk) * HW] = v;
        }
    }
}

// ---------------------------------------------------------------------------
// Deform stage B: out[n][64][HW] = W[64][576] @ samp[n][576][HW] + bias.
// Dynamic smem (66.5 KB): s_s[64][128] samp chunk + s_w2[64][66] dup weights.
// Per k step/thread: 2 LDS128(px) + 4 LDS128(w) + 32 FFMA2 (=64 MACs).
// ---------------------------------------------------------------------------
#define GEMM_SMEM_FLOATS (64 * 128)
#define GEMM_SMEM_BYTES  (GEMM_SMEM_FLOATS * 4 + 64 * 66 * 8)   // 66,560 B

__global__ __launch_bounds__(128) void gemm_k(
    const float* __restrict__ samp, const float* __restrict__ dw,
    const float* __restrict__ db, float* __restrict__ out)
{
    extern __shared__ float sm[];
    float*  s_s  = sm;                              // [64][128]  32 KB
    float2* s_w2 = (float2*)(sm + GEMM_SMEM_FLOATS); // [64][66]  33.8 KB

    const int tid = threadIdx.x;
    const int pxb = blockIdx.x * 128;
    const int n   = blockIdx.y;
    const float* sampn = samp + (size_t)n * 576 * HW;

    const int pg = tid & 15;    // pixel group: 8 px = 4 f32x2 pairs
    const int og = tid >> 4;    // cout group: 8 couts

    unsigned long long acc[8][4];
    #pragma unroll
    for (int o = 0; o < 8; o++)
        #pragma unroll
        for (int p = 0; p < 4; p++) acc[o][p] = 0ull;

    for (int k0 = 0; k0 < 576; k0 += 64) {
        // samp chunk: 64 rows x 128 px, float4-coalesced
        for (int i = tid; i < 64 * 32; i += 128) {
            int r = i >> 5, c4 = i & 31;
            *(float4*)&s_s[r * 128 + c4 * 4] =
                *(const float4*)&sampn[(size_t)(k0 + r) * HW + pxb + c4 * 4];
        }
        // weights: dup pairs, [kk][co] with row stride 66 (pad kills conflicts)
        for (int i = tid; i < 64 * 64; i += 128) {
            int co = i >> 6, kk = i & 63;
            float w = dw[(size_t)co * 576 + k0 + kk];
            s_w2[kk * 66 + co] = make_float2(w, w);
        }
        __syncthreads();

        #pragma unroll 2
        for (int kk = 0; kk < 64; kk++) {
            ulonglong2 p0 = *(const ulonglong2*)&s_s[kk * 128 + pg * 8];
            ulonglong2 p1 = *(const ulonglong2*)&s_s[kk * 128 + pg * 8 + 4];
            unsigned long long wq[8];
            #pragma unroll
            for (int j = 0; j < 4; j++) {
                ulonglong2 wv = *(const ulonglong2*)&s_w2[kk * 66 + og * 8 + 2 * j];
                wq[2 * j]     = wv.x;
                wq[2 * j + 1] = wv.y;
            }
            #pragma unroll
            for (int o = 0; o < 8; o++) {
                ffma2(acc[o][0], wq[o], p0.x);
                ffma2(acc[o][1], wq[o], p0.y);
                ffma2(acc[o][2], wq[o], p1.x);
                ffma2(acc[o][3], wq[o], p1.y);
            }
        }
        __syncthreads();
    }

    // Output placement: bwd n -> x_backward frame n; fwd m -> x_forward frame m+1
    float* outn = (n < 6) ? out + (size_t)n * C * HW
                          : out + (size_t)(7 + (n - 6) + 1) * C * HW;
    #pragma unroll
    for (int o = 0; o < 8; o++) {
        int co = og * 8 + o;
        float bv = db[co];
        float2 a0 = unpack2(acc[o][0]);
        float2 a1 = unpack2(acc[o][1]);
        float2 a2 = unpack2(acc[o][2]);
        float2 a3 = unpack2(acc[o][3]);
        float4 v0 = make_float4(a0.x + bv, a0.y + bv, a1.x + bv, a1.y + bv);
        float4 v1 = make_float4(a2.x + bv, a2.y + bv, a3.x + bv, a3.y + bv);
        size_t base = (size_t)co * HW + pxb + pg * 8;
        *(float4*)&outn[base]     = v0;
        *(float4*)&outn[base + 4] = v1;
    }
}

// ---------------------------------------------------------------------------
// Launch
// ---------------------------------------------------------------------------
extern "C" void kernel_launch(void* const* d_in, const int* in_sizes, int n_in,
                              void* d_out, int out_size)
{
    const float* x  = (const float*)d_in[0];
    const float* fb = (const float*)d_in[1];
    const float* ff = (const float*)d_in[2];
    const float* w1 = (const float*)d_in[3];  const float* b1 = (const float*)d_in[4];
    const float* w2 = (const float*)d_in[5];  const float* b2 = (const float*)d_in[6];
    const float* w3 = (const float*)d_in[7];  const float* b3 = (const float*)d_in[8];
    const float* w4 = (const float*)d_in[9];  const float* b4 = (const float*)d_in[10];
    const float* dw = (const float*)d_in[11]; const float* db = (const float*)d_in[12];
    float* out = (float*)d_out;

    float *h0, *h1, *h2, *o4, *sp;
    cudaGetSymbolAddress((void**)&h0, g_h0);
    cudaGetSymbolAddress((void**)&h1, g_h1);
    cudaGetSymbolAddress((void**)&h2, g_h2);
    cudaGetSymbolAddress((void**)&o4, g_o4);
    cudaGetSymbolAddress((void**)&sp, g_samp);

    {   // Zero only frames 6..7 (bwd[6] and fwd[0])
        int n4 = 2 * C * HW / 4;
        zero_k<<<(n4 + 255) / 256, 256>>>((float4*)(out + (size_t)6 * C * HW), n4);
    }
    warp_concat_k<<<(NB * HW + 255) / 256, 256>>>(x, fb, ff, h0);

    dim3 cb(32, 4);
    conv3x3_k<true ><<<dim3(3, 72, 4),  cb>>>(h0, w1, b1, h1, CIN1, C);
    conv3x3_k<true ><<<dim3(3, 72, 4),  cb>>>(h1, w2, b2, h2, C,    C);
    conv3x3_k<true ><<<dim3(3, 72, 4),  cb>>>(h2, w3, b3, h1, C,    C);
    conv3x3_k<false><<<dim3(3, 72, 27), cb>>>(h1, w4, b4, o4, C, COUT4);

    sample_k<<<dim3(72, 16, NB), 128>>>(x, fb, ff, o4, sp);

    cudaFuncSetAttribute(gemm_k, cudaFuncAttributeMaxDynamicSharedMemorySize,
                         GEMM_SMEM_BYTES);
    gemm_k<<<dim3(72, NB), 128, GEMM_SMEM_BYTES>>>(sp, dw, db, out);
}